// round 14
// baseline (speedup 1.0000x reference)
#include <cuda_runtime.h>
#include <math.h>

#define BATCH 8
#define CHAN 128
#define PLANE 65536          // D*H*W = 4*128*128
#define NBC (BATCH * CHAN)   // 1024

__device__ float g_max[NBC];
__device__ float g_gate[NBC];

// ---------------------------------------------------------------------------
// Kernel 1: per-(b,c) global max. 512 threads/plane, 32 f4/thread in 4 chunks
// of 8 front-batched loads. DEFAULT cache policy: lines retained in L2 so the
// scale kernel (reverse traversal) hits the freshest ~126 MB.
// ---------------------------------------------------------------------------
__global__ __launch_bounds__(512) void reduce_max_kernel(const float* __restrict__ x) {
    const int bc = blockIdx.x;
    const int tid = threadIdx.x;
    const float4* p = reinterpret_cast<const float4*>(x) + (size_t)bc * (PLANE / 4);

    float m = -INFINITY;
    #pragma unroll
    for (int ch = 0; ch < 4; ch++) {
        const int base = ch * 4096 + tid;
        float4 v[8];
        #pragma unroll
        for (int k = 0; k < 8; k++)
            v[k] = p[base + k * 512];
        float a0 = -INFINITY, a1 = -INFINITY;
        #pragma unroll
        for (int k = 0; k < 8; k += 2) {
            a0 = fmaxf(a0, fmaxf(fmaxf(v[k].x, v[k].y), fmaxf(v[k].z, v[k].w)));
            a1 = fmaxf(a1, fmaxf(fmaxf(v[k+1].x, v[k+1].y), fmaxf(v[k+1].z, v[k+1].w)));
        }
        m = fmaxf(m, fmaxf(a0, a1));
    }

    #pragma unroll
    for (int off = 16; off > 0; off >>= 1)
        m = fmaxf(m, __shfl_xor_sync(0xffffffffu, m, off));

    __shared__ float sm[16];
    if ((tid & 31) == 0) sm[tid >> 5] = m;
    __syncthreads();
    if (tid < 16) {
        m = sm[tid];
        #pragma unroll
        for (int off = 8; off > 0; off >>= 1)
            m = fmaxf(m, __shfl_xor_sync(0x0000ffffu, m, off));
        if (tid == 0) g_max[bc] = m;
    }
}

// ---------------------------------------------------------------------------
// Kernel 2: full MLP gate, 8 blocks (one per batch) x 128 threads (verified).
// ---------------------------------------------------------------------------
__global__ __launch_bounds__(128) void mlp_gate_kernel(const float* __restrict__ w1,
                                                       const float* __restrict__ b1,
                                                       const float* __restrict__ w2,
                                                       const float* __restrict__ b2) {
    const int b = blockIdx.x;
    const int o = threadIdx.x;

    __shared__ float gp[CHAN];
    __shared__ float hs[CHAN];
    gp[o] = g_max[b * CHAN + o];
    __syncthreads();

    {
        float acc = __ldg(&b1[o]);
        const float4* wrow = reinterpret_cast<const float4*>(w1 + (size_t)o * CHAN);
        #pragma unroll 8
        for (int q = 0; q < CHAN / 4; q++) {
            float4 w = __ldg(wrow + q);
            const int k = q * 4;
            acc = fmaf(gp[k],     w.x, acc);
            acc = fmaf(gp[k + 1], w.y, acc);
            acc = fmaf(gp[k + 2], w.z, acc);
            acc = fmaf(gp[k + 3], w.w, acc);
        }
        hs[o] = fmaxf(acc, 0.0f);
    }
    __syncthreads();

    {
        float acc = __ldg(&b2[o]);
        const float4* wrow = reinterpret_cast<const float4*>(w2 + (size_t)o * CHAN);
        #pragma unroll 8
        for (int q = 0; q < CHAN / 4; q++) {
            float4 w = __ldg(wrow + q);
            const int k = q * 4;
            acc = fmaf(hs[k],     w.x, acc);
            acc = fmaf(hs[k + 1], w.y, acc);
            acc = fmaf(hs[k + 2], w.z, acc);
            acc = fmaf(hs[k + 3], w.w, acc);
        }
        g_gate[b * CHAN + o] = 1.0f / (1.0f + expf(-acc));
    }
}

// ---------------------------------------------------------------------------
// Kernel 3: out = x * gate[bc], REVERSE traversal (L2 carryover from reduce).
// Loads __ldcs. Stores __stwt: write-through, minimal L2 footprint, so output
// lines don't evict the x lines we haven't read yet.
// ---------------------------------------------------------------------------
__global__ __launch_bounds__(256) void scale_kernel(const float* __restrict__ x,
                                                    float* __restrict__ out) {
    const int rb = 8191 - (int)blockIdx.x;       // reversed region index
    const float g = g_gate[rb >> 3];             // 8 regions per (b,c) plane
    const size_t base = (size_t)rb * 2048 + threadIdx.x;
    const float4* xp = reinterpret_cast<const float4*>(x);
    float4* op = reinterpret_cast<float4*>(out);

    float4 v[8];
    #pragma unroll
    for (int k = 0; k < 8; k++)
        v[k] = __ldcs(xp + base + (size_t)k * 256);

    #pragma unroll
    for (int k = 0; k < 8; k++) {
        v[k].x *= g; v[k].y *= g; v[k].z *= g; v[k].w *= g;
        __stwt(op + base + (size_t)k * 256, v[k]);
    }
}

// ---------------------------------------------------------------------------
extern "C" void kernel_launch(void* const* d_in, const int* in_sizes, int n_in,
                              void* d_out, int out_size) {
    const float* x  = (const float*)d_in[0];
    const float* w1 = (const float*)d_in[1];
    const float* b1 = (const float*)d_in[2];
    const float* w2 = (const float*)d_in[3];
    const float* b2 = (const float*)d_in[4];
    float* out = (float*)d_out;

    reduce_max_kernel<<<NBC, 512>>>(x);
    mlp_gate_kernel<<<BATCH, 128>>>(w1, b1, w2, b2);
    scale_kernel<<<8192, 256>>>(x, out);
}

// round 15
// speedup vs baseline: 1.0256x; 1.0256x over previous
#include <cuda_runtime.h>
#include <math.h>

#define BATCH 8
#define CHAN 128
#define PLANE 65536          // D*H*W = 4*128*128
#define NBC (BATCH * CHAN)   // 1024

__device__ float g_max[NBC];
__device__ float g_gate[NBC];

// ---------------------------------------------------------------------------
// Kernel 1: per-(b,c) global max (verified 41-42us, ~83% spec). Default cache
// policy: leave freshest ~126MB of x in L2 for the reverse-order scale.
// ---------------------------------------------------------------------------
__global__ __launch_bounds__(512) void reduce_max_kernel(const float* __restrict__ x) {
    const int bc = blockIdx.x;
    const int tid = threadIdx.x;
    const float4* p = reinterpret_cast<const float4*>(x) + (size_t)bc * (PLANE / 4);

    float m = -INFINITY;
    #pragma unroll
    for (int ch = 0; ch < 4; ch++) {
        const int base = ch * 4096 + tid;
        float4 v[8];
        #pragma unroll
        for (int k = 0; k < 8; k++)
            v[k] = p[base + k * 512];
        float a0 = -INFINITY, a1 = -INFINITY;
        #pragma unroll
        for (int k = 0; k < 8; k += 2) {
            a0 = fmaxf(a0, fmaxf(fmaxf(v[k].x, v[k].y), fmaxf(v[k].z, v[k].w)));
            a1 = fmaxf(a1, fmaxf(fmaxf(v[k+1].x, v[k+1].y), fmaxf(v[k+1].z, v[k+1].w)));
        }
        m = fmaxf(m, fmaxf(a0, a1));
    }

    #pragma unroll
    for (int off = 16; off > 0; off >>= 1)
        m = fmaxf(m, __shfl_xor_sync(0xffffffffu, m, off));

    __shared__ float sm[16];
    if ((tid & 31) == 0) sm[tid >> 5] = m;
    __syncthreads();
    if (tid < 16) {
        m = sm[tid];
        #pragma unroll
        for (int off = 8; off > 0; off >>= 1)
            m = fmaxf(m, __shfl_xor_sync(0x0000ffffu, m, off));
        if (tid == 0) g_max[bc] = m;
    }
}

// ---------------------------------------------------------------------------
// Kernel 2: full MLP gate, 8 blocks x 128 threads. PDL: weight rows for
// phase 1 are prefetched BEFORE cudaGridDependencySynchronize(); only the
// g_max read waits for reduce completion.
// ---------------------------------------------------------------------------
__global__ __launch_bounds__(128) void mlp_gate_kernel(const float* __restrict__ w1,
                                                       const float* __restrict__ b1,
                                                       const float* __restrict__ w2,
                                                       const float* __restrict__ b2) {
    const int b = blockIdx.x;
    const int o = threadIdx.x;

    __shared__ float gp[CHAN];
    __shared__ float hs[CHAN];

    // prefetch phase-1 weights while reduce finishes
    float4 wr[CHAN / 4];
    const float4* wrow1 = reinterpret_cast<const float4*>(w1 + (size_t)o * CHAN);
    #pragma unroll 8
    for (int q = 0; q < CHAN / 4; q++)
        wr[q] = __ldg(wrow1 + q);
    const float bias1 = __ldg(&b1[o]);

    cudaGridDependencySynchronize();        // wait for reduce's g_max

    gp[o] = __ldcg(&g_max[b * CHAN + o]);
    __syncthreads();

    {
        float acc = bias1;
        #pragma unroll 8
        for (int q = 0; q < CHAN / 4; q++) {
            const int k = q * 4;
            acc = fmaf(gp[k],     wr[q].x, acc);
            acc = fmaf(gp[k + 1], wr[q].y, acc);
            acc = fmaf(gp[k + 2], wr[q].z, acc);
            acc = fmaf(gp[k + 3], wr[q].w, acc);
        }
        hs[o] = fmaxf(acc, 0.0f);
    }
    __syncthreads();

    {
        float acc = __ldg(&b2[o]);
        const float4* wrow2 = reinterpret_cast<const float4*>(w2 + (size_t)o * CHAN);
        #pragma unroll 8
        for (int q = 0; q < CHAN / 4; q++) {
            float4 w = __ldg(wrow2 + q);
            const int k = q * 4;
            acc = fmaf(hs[k],     w.x, acc);
            acc = fmaf(hs[k + 1], w.y, acc);
            acc = fmaf(hs[k + 2], w.z, acc);
            acc = fmaf(hs[k + 3], w.w, acc);
        }
        g_gate[b * CHAN + o] = 1.0f / (1.0f + expf(-acc));
    }
}

// ---------------------------------------------------------------------------
// Kernel 3: out = x * gate, reverse traversal, __ldcs/__stcs (verified R13).
// PDL: the 8 independent x-loads are issued BEFORE the grid-dependency sync;
// only the single gate load waits for mlp. The mlp's ~4us hides under the
// first wave's load issue.
// ---------------------------------------------------------------------------
__global__ __launch_bounds__(256) void scale_kernel(const float* __restrict__ x,
                                                    float* __restrict__ out) {
    const int rb = 8191 - (int)blockIdx.x;       // reversed region index
    const size_t base = (size_t)rb * 2048 + threadIdx.x;
    const float4* xp = reinterpret_cast<const float4*>(x);
    float4* op = reinterpret_cast<float4*>(out);

    float4 v[8];
    #pragma unroll
    for (int k = 0; k < 8; k++)
        v[k] = __ldcs(xp + base + (size_t)k * 256);

    cudaGridDependencySynchronize();             // wait for mlp's g_gate
    const float g = __ldcg(&g_gate[rb >> 3]);

    #pragma unroll
    for (int k = 0; k < 8; k++) {
        v[k].x *= g; v[k].y *= g; v[k].z *= g; v[k].w *= g;
        __stcs(op + base + (size_t)k * 256, v[k]);
    }
}

// ---------------------------------------------------------------------------
extern "C" void kernel_launch(void* const* d_in, const int* in_sizes, int n_in,
                              void* d_out, int out_size) {
    const float* x  = (const float*)d_in[0];
    const float* w1 = (const float*)d_in[1];
    const float* b1 = (const float*)d_in[2];
    const float* w2 = (const float*)d_in[3];
    const float* b2 = (const float*)d_in[4];
    float* out = (float*)d_out;

    reduce_max_kernel<<<NBC, 512>>>(x);

    cudaLaunchAttribute pdl[1];
    pdl[0].id = cudaLaunchAttributeProgrammaticStreamSerialization;
    pdl[0].val.programmaticStreamSerializationAllowed = 1;

    {   // mlp: PDL-dependent on reduce
        cudaLaunchConfig_t cfg = {};
        cfg.gridDim  = dim3(BATCH, 1, 1);
        cfg.blockDim = dim3(128, 1, 1);
        cfg.stream   = 0;
        cfg.attrs    = pdl;
        cfg.numAttrs = 1;
        cudaLaunchKernelEx(&cfg, mlp_gate_kernel, w1, b1, w2, b2);
    }
    {   // scale: PDL-dependent on mlp
        cudaLaunchConfig_t cfg = {};
        cfg.gridDim  = dim3(8192, 1, 1);
        cfg.blockDim = dim3(256, 1, 1);
        cfg.stream   = 0;
        cfg.attrs    = pdl;
        cfg.numAttrs = 1;
        cudaLaunchKernelEx(&cfg, scale_kernel, x, out);
    }
}